// round 13
// baseline (speedup 1.0000x reference)
#include <cuda_runtime.h>
#include <math.h>

// Problem constants
#define N_A   512
#define N_X   512
#define T_X   1024
#define M_B   64
#define NCOLS 65536          // M_B * T_X
#define A_ELEMS 33554432     // 512*64*1024
#define CH    8              // timestep chunk staged in SMEM

// ---------------------------------------------------------------------------
// Packed f32x2 helpers (sm_103a FFMA2 — ptxas never auto-generates these)
// ---------------------------------------------------------------------------
__device__ __forceinline__ unsigned long long pack2(float lo, float hi) {
    unsigned long long r;
    asm("mov.b64 %0, {%1, %2};" : "=l"(r) : "f"(lo), "f"(hi));
    return r;
}
__device__ __forceinline__ float2 unpack2(unsigned long long v) {
    float2 r;
    asm("mov.b64 {%0, %1}, %2;" : "=f"(r.x), "=f"(r.y) : "l"(v));
    return r;
}
// d = a * b + d   (two independent fp32 FMAs per instruction)
__device__ __forceinline__ void fma2(unsigned long long& d,
                                     unsigned long long a,
                                     unsigned long long b) {
    asm("fma.rn.f32x2 %0, %1, %2, %3;" : "=l"(d) : "l"(a), "l"(b), "l"(d));
}

// ---------------------------------------------------------------------------
// Persistent-kernel state (small; endorsed scratch mechanism)
// ---------------------------------------------------------------------------
__device__ __align__(16) float g_abuf[2][N_A * M_B];  // ping-pong a_t (compact 512x64)
__device__ unsigned g_bar_cnt = 0;
__device__ unsigned g_bar_gen = 0;

#define REC_BLOCKS 128

// Light grid barrier: acquire/release atomics, no membar.gpu, no nanosleep.
__device__ __forceinline__ void grid_barrier() {
    __syncthreads();
    if (threadIdx.x == 0) {
        unsigned my;
        asm volatile("ld.acquire.gpu.u32 %0, [%1];"
                     : "=r"(my) : "l"(&g_bar_gen) : "memory");
        unsigned prev;
        asm volatile("atom.acq_rel.gpu.add.u32 %0, [%1], %2;"
                     : "=r"(prev) : "l"(&g_bar_cnt), "r"(1u) : "memory");
        if (prev == REC_BLOCKS - 1) {
            asm volatile("st.relaxed.gpu.u32 [%0], %1;"
                         :: "l"(&g_bar_cnt), "r"(0u) : "memory");
            asm volatile("red.release.gpu.add.u32 [%0], %1;"
                         :: "l"(&g_bar_gen), "r"(1u) : "memory");
        } else {
            unsigned g;
            do {
                asm volatile("ld.acquire.gpu.u32 %0, [%1];"
                             : "=r"(g) : "l"(&g_bar_gen) : "memory");
            } while (g == my);
        }
    }
    __syncthreads();
}

// ---------------------------------------------------------------------------
// SGEMM: C[512, N] = A[512,512] @ B[512, N] + bias[512]
// 128x128 CTA tile, BK=8, 256 threads, 8x8 per thread, double-buffered SMEM.
// Inner product uses FFMA2: accumulators paired across adjacent n-columns.
// FMA sequence per output element is identical to the scalar version
// (bitwise-identical results).
// ---------------------------------------------------------------------------
__global__ void __launch_bounds__(256) sgemm512_bias(
    const float* __restrict__ A, const float* __restrict__ B,
    float* __restrict__ C, const float* __restrict__ bias, int N)
{
    const int K = 512;
    __shared__ __align__(16) float As[2][8][128];
    __shared__ __align__(16) float Bs[2][8][128];

    int tid = threadIdx.x;
    int mBlock = blockIdx.y * 128;
    int nBlock = blockIdx.x * 128;

    int a_row = tid >> 1;
    int a_k4  = (tid & 1) << 2;
    int b_k   = tid >> 5;
    int b_col = (tid & 31) << 2;

    int tr = tid >> 4;            // 0..15
    int tc = tid & 15;            // 0..15
    int m0 = tr * 8, n0 = tc * 8;

    // acc2[r][p] = packed pair (C[r][2p], C[r][2p+1]); (0.0f,0.0f) == 0ull
    unsigned long long acc2[8][4];
    #pragma unroll
    for (int r = 0; r < 8; ++r)
        #pragma unroll
        for (int c = 0; c < 4; ++c) acc2[r][c] = 0ull;

    const float* Aptr = A + (size_t)(mBlock + a_row) * K + a_k4;
    const float* Bptr = B + (size_t)b_k * N + nBlock + b_col;

    // prologue: tile 0 -> buffer 0
    float4 av = *(const float4*)(Aptr);
    float4 bv = *(const float4*)(Bptr);
    As[0][a_k4 + 0][a_row] = av.x;
    As[0][a_k4 + 1][a_row] = av.y;
    As[0][a_k4 + 2][a_row] = av.z;
    As[0][a_k4 + 3][a_row] = av.w;
    *(float4*)&Bs[0][b_k][b_col] = bv;
    __syncthreads();

    for (int it = 0; it < K / 8; ++it) {
        int cur = it & 1;
        if (it < K / 8 - 1) {
            av = *(const float4*)(Aptr + (it + 1) * 8);
            bv = *(const float4*)(Bptr + (size_t)(it + 1) * 8 * N);
        }

        #pragma unroll
        for (int kk = 0; kk < 8; ++kk) {
            float4 a0v = *(const float4*)&As[cur][kk][m0];
            float4 a1v = *(const float4*)&As[cur][kk][m0 + 4];
            // B pairs read directly as b64 lanes (same LDS.128s as before)
            ulonglong2 b01 = *(const ulonglong2*)&Bs[cur][kk][n0];
            ulonglong2 b45 = *(const ulonglong2*)&Bs[cur][kk][n0 + 4];
            float am[8] = {a0v.x, a0v.y, a0v.z, a0v.w, a1v.x, a1v.y, a1v.z, a1v.w};
            #pragma unroll
            for (int r = 0; r < 8; ++r) {
                unsigned long long ar = pack2(am[r], am[r]);
                fma2(acc2[r][0], ar, b01.x);
                fma2(acc2[r][1], ar, b01.y);
                fma2(acc2[r][2], ar, b45.x);
                fma2(acc2[r][3], ar, b45.y);
            }
        }

        if (it < K / 8 - 1) {
            int nxt = cur ^ 1;
            As[nxt][a_k4 + 0][a_row] = av.x;
            As[nxt][a_k4 + 1][a_row] = av.y;
            As[nxt][a_k4 + 2][a_row] = av.z;
            As[nxt][a_k4 + 3][a_row] = av.w;
            *(float4*)&Bs[nxt][b_k][b_col] = bv;
            __syncthreads();
        }
    }

    #pragma unroll
    for (int r = 0; r < 8; ++r) {
        int row = mBlock + m0 + r;
        float bvl = bias[row];
        float* cp = C + (size_t)row * N + nBlock + n0;
        float2 p0 = unpack2(acc2[r][0]);
        float2 p1 = unpack2(acc2[r][1]);
        float2 p2 = unpack2(acc2[r][2]);
        float2 p3 = unpack2(acc2[r][3]);
        float4 o0 = make_float4(p0.x + bvl, p0.y + bvl, p1.x + bvl, p1.y + bvl);
        float4 o1 = make_float4(p2.x + bvl, p2.y + bvl, p3.x + bvl, p3.y + bvl);
        *(float4*)cp = o0;
        *(float4*)(cp + 4) = o1;
    }
}

// ---------------------------------------------------------------------------
// Recurrence: persistent kernel. 128 CTAs x 256 threads, 2D tiled.
// Grid = 32 row-groups x 4 col-groups; CTA tile = 16 rows x 16 cols.
// Waa block lives in REGISTERS as pre-packed f32x2 row pairs:
//   wlo[kk] = (Waa[r0+rg*4+0][k], Waa[r0+rg*4+1][k])
//   whi[kk] = (Waa[r0+rg*4+2][k], Waa[r0+rg*4+3][k])
// Per step per thread: 32 x LDG.128 of a_prev + 4 dup-packs + 8 FFMA2 per k
// (half the FMA-issue of the scalar version; identical FMA order per element).
// Z / a-output staged through SMEM in CH-step chunks.
// ---------------------------------------------------------------------------
__global__ void __launch_bounds__(256, 1) rnn_recurrence(
    const float* __restrict__ Waa, const float* __restrict__ a0,
    const float* __restrict__ Z, float* __restrict__ out_a)
{
    __shared__ __align__(16) float red[16 * 260];   // [s][lr*16+lj], padded
    __shared__ float sZ[CH * 257];                  // [tt][pair], padded
    __shared__ float sA[CH * 257];

    int tid = threadIdx.x;
    int rb = blockIdx.x >> 2;
    int cb = blockIdx.x & 3;
    int r0 = rb * 16;
    int j0 = cb * 16;

    int jq = tid & 3;          // col quad: cols j0 + jq*4 .. +3
    int rg = (tid >> 2) & 3;   // row group: rows r0 + rg*4 .. +3
    int s  = tid >> 4;         // k-slice: k in [32s, 32s+32)

    // Waa block -> packed registers (one-time; L1-served)
    unsigned long long wlo[32], whi[32];
    {
        const float* w0 = Waa + (size_t)(r0 + rg * 4 + 0) * 512 + s * 32;
        const float* w1 = Waa + (size_t)(r0 + rg * 4 + 1) * 512 + s * 32;
        const float* w2 = Waa + (size_t)(r0 + rg * 4 + 2) * 512 + s * 32;
        const float* w3 = Waa + (size_t)(r0 + rg * 4 + 3) * 512 + s * 32;
        #pragma unroll
        for (int kk = 0; kk < 32; ++kk) {
            wlo[kk] = pack2(w0[kk], w1[kk]);
            whi[kk] = pack2(w2[kk], w3[kk]);
        }
    }

    int out_lr = tid >> 4;     // 0..15 local row
    int out_lj = tid & 15;     // 0..15 local col
    int gr = r0 + out_lr;
    int gj = j0 + out_lj;

    int aq = (j0 >> 2) + jq;   // float4 column index into a_prev (64 floats/row)

    for (int c = 0; c < T_X / CH; ++c) {
        int t0 = c * CH;

        // Stage Z chunk: 16 lr x 16 lj x CH t  (two float4 per thread)
        #pragma unroll
        for (int i = 0; i < 2; ++i) {
            int e = tid + i * 256;
            int p = e >> 1;                 // pair 0..255: lr = p>>4, lj = p&15
            int q = e & 1;                  // which half of the 8 timesteps
            int lr2 = p >> 4, lj2 = p & 15;
            float4 v = *(const float4*)(Z + (size_t)(r0 + lr2) * NCOLS
                                          + (j0 + lj2) * T_X + t0 + q * 4);
            sZ[(q * 4 + 0) * 257 + p] = v.x;
            sZ[(q * 4 + 1) * 257 + p] = v.y;
            sZ[(q * 4 + 2) * 257 + p] = v.z;
            sZ[(q * 4 + 3) * 257 + p] = v.w;
        }
        // ordered before first use by step-0's reduction __syncthreads

        for (int tt = 0; tt < CH; ++tt) {
            int t = t0 + tt;
            const float4* ap4 = (const float4*)((t == 0) ? a0 : g_abuf[(t - 1) & 1]);

            // acc2[rp][cc] = packed rows (2rp, 2rp+1) for local column cc
            unsigned long long acc2[2][4];
            #pragma unroll
            for (int rp = 0; rp < 2; ++rp)
                #pragma unroll
                for (int cc = 0; cc < 4; ++cc) acc2[rp][cc] = 0ull;

            #pragma unroll
            for (int kk = 0; kk < 32; ++kk) {
                float4 avv = ap4[(s * 32 + kk) * 16 + aq];  // a_prev[k, 4 cols]
                unsigned long long ax = pack2(avv.x, avv.x);
                unsigned long long ay = pack2(avv.y, avv.y);
                unsigned long long az = pack2(avv.z, avv.z);
                unsigned long long aw = pack2(avv.w, avv.w);
                fma2(acc2[0][0], wlo[kk], ax);
                fma2(acc2[0][1], wlo[kk], ay);
                fma2(acc2[0][2], wlo[kk], az);
                fma2(acc2[0][3], wlo[kk], aw);
                fma2(acc2[1][0], whi[kk], ax);
                fma2(acc2[1][1], whi[kk], ay);
                fma2(acc2[1][2], whi[kk], az);
                fma2(acc2[1][3], whi[kk], aw);
            }

            // unpack + store partials: red[s][(rg*4+r)*16 + jq*4 .. +3]
            #pragma unroll
            for (int rp = 0; rp < 2; ++rp) {
                float2 c0 = unpack2(acc2[rp][0]);
                float2 c1 = unpack2(acc2[rp][1]);
                float2 c2 = unpack2(acc2[rp][2]);
                float2 c3 = unpack2(acc2[rp][3]);
                float4 vlo = make_float4(c0.x, c1.x, c2.x, c3.x);  // row 2rp
                float4 vhi = make_float4(c0.y, c1.y, c2.y, c3.y);  // row 2rp+1
                *(float4*)&red[s * 260 + (rg * 4 + 2 * rp + 0) * 16 + jq * 4] = vlo;
                *(float4*)&red[s * 260 + (rg * 4 + 2 * rp + 1) * 16 + jq * 4] = vhi;
            }
            __syncthreads();

            float sum = 0.0f;
            #pragma unroll
            for (int ss = 0; ss < 16; ++ss)
                sum += red[ss * 260 + out_lr * 16 + out_lj];

            float h = tanhf(sum + sZ[tt * 257 + tid]);
            g_abuf[t & 1][gr * 64 + gj] = h;    // compact state (next step's input)
            sA[tt * 257 + tid] = h;             // staged final-layout output

            if (t != T_X - 1) grid_barrier();   // includes leading __syncthreads
        }

        if (c == T_X / CH - 1) __syncthreads(); // last chunk lacks trailing barrier

        // Flush a chunk (coalesced float4 over t)
        #pragma unroll
        for (int i = 0; i < 2; ++i) {
            int e = tid + i * 256;
            int p = e >> 1;
            int q = e & 1;
            int lr2 = p >> 4, lj2 = p & 15;
            float4 v;
            v.x = sA[(q * 4 + 0) * 257 + p];
            v.y = sA[(q * 4 + 1) * 257 + p];
            v.z = sA[(q * 4 + 2) * 257 + p];
            v.w = sA[(q * 4 + 3) * 257 + p];
            *(float4*)(out_a + (size_t)(r0 + lr2) * NCOLS
                             + (j0 + lj2) * T_X + t0 + q * 4) = v;
        }
        // sA/sZ reuse next chunk ordered by next step's reduction __syncthreads
    }
}

// ---------------------------------------------------------------------------
// Softmax over the batch axis m (stride 1024 in memory), 64 elements/group.
// ---------------------------------------------------------------------------
__global__ void __launch_bounds__(256) softmax_batch(float* __restrict__ Y)
{
    int g = blockIdx.x * blockDim.x + threadIdx.x;   // 0 .. 512*1024-1
    int i = g >> 10, t = g & 1023;
    float* base = Y + (size_t)i * NCOLS + t;

    float v[64];
    float mx = -INFINITY;
    #pragma unroll
    for (int j = 0; j < 64; ++j) {
        v[j] = base[j * T_X];
        mx = fmaxf(mx, v[j]);
    }
    float sum = 0.0f;
    #pragma unroll
    for (int j = 0; j < 64; ++j) {
        v[j] = __expf(v[j] - mx);
        sum += v[j];
    }
    float inv = 1.0f / sum;
    #pragma unroll
    for (int j = 0; j < 64; ++j)
        base[j * T_X] = v[j] * inv;
}

// ---------------------------------------------------------------------------
// Launch: GEMM1 (Z into y-half of d_out) -> recurrence -> GEMM2 -> softmax
// ---------------------------------------------------------------------------
extern "C" void kernel_launch(void* const* d_in, const int* in_sizes, int n_in,
                              void* d_out, int out_size)
{
    const float* x   = (const float*)d_in[0];   // (512, 64, 1024) = 512 x 65536
    const float* a0  = (const float*)d_in[1];   // (512, 64)
    const float* Waa = (const float*)d_in[2];   // (512, 512)
    const float* Wax = (const float*)d_in[3];   // (512, 512)
    const float* Wya = (const float*)d_in[4];   // (512, 512)
    const float* ba  = (const float*)d_in[5];   // (512,)
    const float* by  = (const float*)d_in[6];   // (512,)

    float* out_a = (float*)d_out;               // first 512*64*1024 floats
    float* out_y = out_a + A_ELEMS;             // second half; also Z scratch

    dim3 gemm_grid(NCOLS / 128, N_A / 128);     // (512, 4)

    // 1) Z = Wax @ X + ba  (written into y-half, same [i, j*1024+t] layout)
    sgemm512_bias<<<gemm_grid, 256>>>(Wax, x, out_y, ba, NCOLS);

    // 2) sequential recurrence -> out_a
    rnn_recurrence<<<REC_BLOCKS, 256>>>(Waa, a0, out_y, out_a);

    // 3) logits = Wya @ A + by  (overwrites Z in y-half)
    sgemm512_bias<<<gemm_grid, 256>>>(Wya, out_a, out_y, by, NCOLS);

    // 4) softmax over batch axis
    softmax_batch<<<(N_X * T_X) / 256, 256>>>(out_y);
}

// round 15
// speedup vs baseline: 1.0035x; 1.0035x over previous
#include <cuda_runtime.h>
#include <math.h>

// Problem constants
#define N_A   512
#define N_X   512
#define T_X   1024
#define M_B   64
#define NCOLS 65536          // M_B * T_X
#define A_ELEMS 33554432     // 512*64*1024
#define CH    8              // timestep chunk staged in SMEM

// ---------------------------------------------------------------------------
// Packed f32x2 helpers (sm_103a FFMA2 — ptxas never auto-generates these)
// ---------------------------------------------------------------------------
__device__ __forceinline__ unsigned long long pack2(float lo, float hi) {
    unsigned long long r;
    asm("mov.b64 %0, {%1, %2};" : "=l"(r) : "f"(lo), "f"(hi));
    return r;
}
__device__ __forceinline__ float2 unpack2(unsigned long long v) {
    float2 r;
    asm("mov.b64 {%0, %1}, %2;" : "=f"(r.x), "=f"(r.y) : "l"(v));
    return r;
}
// d = a * b + d   (two independent fp32 FMAs per instruction)
__device__ __forceinline__ void fma2(unsigned long long& d,
                                     unsigned long long a,
                                     unsigned long long b) {
    asm("fma.rn.f32x2 %0, %1, %2, %3;" : "=l"(d) : "l"(a), "l"(b), "l"(d));
}

// ---------------------------------------------------------------------------
// Persistent-kernel state (small; endorsed scratch mechanism)
// ---------------------------------------------------------------------------
__device__ __align__(16) float g_abuf[2][N_A * M_B];  // ping-pong a_t (compact 512x64)
__device__ unsigned g_bar_cnt = 0;
__device__ unsigned g_bar_gen = 0;

#define REC_BLOCKS 128

// Light grid barrier: acquire/release atomics, no membar.gpu, no nanosleep.
__device__ __forceinline__ void grid_barrier() {
    __syncthreads();
    if (threadIdx.x == 0) {
        unsigned my;
        asm volatile("ld.acquire.gpu.u32 %0, [%1];"
                     : "=r"(my) : "l"(&g_bar_gen) : "memory");
        unsigned prev;
        asm volatile("atom.acq_rel.gpu.add.u32 %0, [%1], %2;"
                     : "=r"(prev) : "l"(&g_bar_cnt), "r"(1u) : "memory");
        if (prev == REC_BLOCKS - 1) {
            asm volatile("st.relaxed.gpu.u32 [%0], %1;"
                         :: "l"(&g_bar_cnt), "r"(0u) : "memory");
            asm volatile("red.release.gpu.add.u32 [%0], %1;"
                         :: "l"(&g_bar_gen), "r"(1u) : "memory");
        } else {
            unsigned g;
            do {
                asm volatile("ld.acquire.gpu.u32 %0, [%1];"
                             : "=r"(g) : "l"(&g_bar_gen) : "memory");
            } while (g == my);
        }
    }
    __syncthreads();
}

// ---------------------------------------------------------------------------
// SGEMM: C[512, N] = A[512,512] @ B[512, N] + bias[512]
// 128x128 CTA tile, BK=8, 256 threads, 8x8 per thread, double-buffered SMEM.
// Inner product uses FFMA2: accumulators paired across adjacent n-columns.
// FMA sequence per output element is identical to the scalar version
// (bitwise-identical results).
// ---------------------------------------------------------------------------
__global__ void __launch_bounds__(256) sgemm512_bias(
    const float* __restrict__ A, const float* __restrict__ B,
    float* __restrict__ C, const float* __restrict__ bias, int N)
{
    const int K = 512;
    __shared__ __align__(16) float As[2][8][128];
    __shared__ __align__(16) float Bs[2][8][128];

    int tid = threadIdx.x;
    int mBlock = blockIdx.y * 128;
    int nBlock = blockIdx.x * 128;

    int a_row = tid >> 1;
    int a_k4  = (tid & 1) << 2;
    int b_k   = tid >> 5;
    int b_col = (tid & 31) << 2;

    int tr = tid >> 4;            // 0..15
    int tc = tid & 15;            // 0..15
    int m0 = tr * 8, n0 = tc * 8;

    // acc2[r][p] = packed pair (C[r][2p], C[r][2p+1]); (0.0f,0.0f) == 0ull
    unsigned long long acc2[8][4];
    #pragma unroll
    for (int r = 0; r < 8; ++r)
        #pragma unroll
        for (int c = 0; c < 4; ++c) acc2[r][c] = 0ull;

    const float* Aptr = A + (size_t)(mBlock + a_row) * K + a_k4;
    const float* Bptr = B + (size_t)b_k * N + nBlock + b_col;

    // prologue: tile 0 -> buffer 0
    float4 av = *(const float4*)(Aptr);
    float4 bv = *(const float4*)(Bptr);
    As[0][a_k4 + 0][a_row] = av.x;
    As[0][a_k4 + 1][a_row] = av.y;
    As[0][a_k4 + 2][a_row] = av.z;
    As[0][a_k4 + 3][a_row] = av.w;
    *(float4*)&Bs[0][b_k][b_col] = bv;
    __syncthreads();

    for (int it = 0; it < K / 8; ++it) {
        int cur = it & 1;
        if (it < K / 8 - 1) {
            av = *(const float4*)(Aptr + (it + 1) * 8);
            bv = *(const float4*)(Bptr + (size_t)(it + 1) * 8 * N);
        }

        #pragma unroll
        for (int kk = 0; kk < 8; ++kk) {
            float4 a0v = *(const float4*)&As[cur][kk][m0];
            float4 a1v = *(const float4*)&As[cur][kk][m0 + 4];
            // B pairs read directly as b64 lanes (same LDS.128s as before)
            ulonglong2 b01 = *(const ulonglong2*)&Bs[cur][kk][n0];
            ulonglong2 b45 = *(const ulonglong2*)&Bs[cur][kk][n0 + 4];
            float am[8] = {a0v.x, a0v.y, a0v.z, a0v.w, a1v.x, a1v.y, a1v.z, a1v.w};
            #pragma unroll
            for (int r = 0; r < 8; ++r) {
                unsigned long long ar = pack2(am[r], am[r]);
                fma2(acc2[r][0], ar, b01.x);
                fma2(acc2[r][1], ar, b01.y);
                fma2(acc2[r][2], ar, b45.x);
                fma2(acc2[r][3], ar, b45.y);
            }
        }

        if (it < K / 8 - 1) {
            int nxt = cur ^ 1;
            As[nxt][a_k4 + 0][a_row] = av.x;
            As[nxt][a_k4 + 1][a_row] = av.y;
            As[nxt][a_k4 + 2][a_row] = av.z;
            As[nxt][a_k4 + 3][a_row] = av.w;
            *(float4*)&Bs[nxt][b_k][b_col] = bv;
            __syncthreads();
        }
    }

    #pragma unroll
    for (int r = 0; r < 8; ++r) {
        int row = mBlock + m0 + r;
        float bvl = bias[row];
        float* cp = C + (size_t)row * N + nBlock + n0;
        float2 p0 = unpack2(acc2[r][0]);
        float2 p1 = unpack2(acc2[r][1]);
        float2 p2 = unpack2(acc2[r][2]);
        float2 p3 = unpack2(acc2[r][3]);
        float4 o0 = make_float4(p0.x + bvl, p0.y + bvl, p1.x + bvl, p1.y + bvl);
        float4 o1 = make_float4(p2.x + bvl, p2.y + bvl, p3.x + bvl, p3.y + bvl);
        *(float4*)cp = o0;
        *(float4*)(cp + 4) = o1;
    }
}

// ---------------------------------------------------------------------------
// Recurrence: persistent kernel. 128 CTAs x 256 threads, 2D tiled.
// Grid = 32 row-groups x 4 col-groups; CTA tile = 16 rows x 16 cols.
// Waa block lives in REGISTERS as pre-packed f32x2 row pairs:
//   wlo[kk] = (Waa[r0+rg*4+0][k], Waa[r0+rg*4+1][k])
//   whi[kk] = (Waa[r0+rg*4+2][k], Waa[r0+rg*4+3][k])
// Per step per thread: 32 x LDG.128 of a_prev + 4 dup-packs + 8 FFMA2 per k
// (half the FMA-issue of the scalar version; identical FMA order per element).
// Z / a-output staged through SMEM in CH-step chunks.
// ---------------------------------------------------------------------------
__global__ void __launch_bounds__(256, 1) rnn_recurrence(
    const float* __restrict__ Waa, const float* __restrict__ a0,
    const float* __restrict__ Z, float* __restrict__ out_a)
{
    __shared__ __align__(16) float red[16 * 260];   // [s][lr*16+lj], padded
    __shared__ float sZ[CH * 257];                  // [tt][pair], padded
    __shared__ float sA[CH * 257];

    int tid = threadIdx.x;
    int rb = blockIdx.x >> 2;
    int cb = blockIdx.x & 3;
    int r0 = rb * 16;
    int j0 = cb * 16;

    int jq = tid & 3;          // col quad: cols j0 + jq*4 .. +3
    int rg = (tid >> 2) & 3;   // row group: rows r0 + rg*4 .. +3
    int s  = tid >> 4;         // k-slice: k in [32s, 32s+32)

    // Waa block -> packed registers (one-time; L1-served)
    unsigned long long wlo[32], whi[32];
    {
        const float* w0 = Waa + (size_t)(r0 + rg * 4 + 0) * 512 + s * 32;
        const float* w1 = Waa + (size_t)(r0 + rg * 4 + 1) * 512 + s * 32;
        const float* w2 = Waa + (size_t)(r0 + rg * 4 + 2) * 512 + s * 32;
        const float* w3 = Waa + (size_t)(r0 + rg * 4 + 3) * 512 + s * 32;
        #pragma unroll
        for (int kk = 0; kk < 32; ++kk) {
            wlo[kk] = pack2(w0[kk], w1[kk]);
            whi[kk] = pack2(w2[kk], w3[kk]);
        }
    }

    int out_lr = tid >> 4;     // 0..15 local row
    int out_lj = tid & 15;     // 0..15 local col
    int gr = r0 + out_lr;
    int gj = j0 + out_lj;

    int aq = (j0 >> 2) + jq;   // float4 column index into a_prev (64 floats/row)

    for (int c = 0; c < T_X / CH; ++c) {
        int t0 = c * CH;

        // Stage Z chunk: 16 lr x 16 lj x CH t  (two float4 per thread)
        #pragma unroll
        for (int i = 0; i < 2; ++i) {
            int e = tid + i * 256;
            int p = e >> 1;                 // pair 0..255: lr = p>>4, lj = p&15
            int q = e & 1;                  // which half of the 8 timesteps
            int lr2 = p >> 4, lj2 = p & 15;
            float4 v = *(const float4*)(Z + (size_t)(r0 + lr2) * NCOLS
                                          + (j0 + lj2) * T_X + t0 + q * 4);
            sZ[(q * 4 + 0) * 257 + p] = v.x;
            sZ[(q * 4 + 1) * 257 + p] = v.y;
            sZ[(q * 4 + 2) * 257 + p] = v.z;
            sZ[(q * 4 + 3) * 257 + p] = v.w;
        }
        // ordered before first use by step-0's reduction __syncthreads

        for (int tt = 0; tt < CH; ++tt) {
            int t = t0 + tt;
            const float4* ap4 = (const float4*)((t == 0) ? a0 : g_abuf[(t - 1) & 1]);

            // acc2[rp][cc] = packed rows (2rp, 2rp+1) for local column cc
            unsigned long long acc2[2][4];
            #pragma unroll
            for (int rp = 0; rp < 2; ++rp)
                #pragma unroll
                for (int cc = 0; cc < 4; ++cc) acc2[rp][cc] = 0ull;

            #pragma unroll
            for (int kk = 0; kk < 32; ++kk) {
                float4 avv = ap4[(s * 32 + kk) * 16 + aq];  // a_prev[k, 4 cols]
                unsigned long long ax = pack2(avv.x, avv.x);
                unsigned long long ay = pack2(avv.y, avv.y);
                unsigned long long az = pack2(avv.z, avv.z);
                unsigned long long aw = pack2(avv.w, avv.w);
                fma2(acc2[0][0], wlo[kk], ax);
                fma2(acc2[0][1], wlo[kk], ay);
                fma2(acc2[0][2], wlo[kk], az);
                fma2(acc2[0][3], wlo[kk], aw);
                fma2(acc2[1][0], whi[kk], ax);
                fma2(acc2[1][1], whi[kk], ay);
                fma2(acc2[1][2], whi[kk], az);
                fma2(acc2[1][3], whi[kk], aw);
            }

            // unpack + store partials: red[s][(rg*4+r)*16 + jq*4 .. +3]
            #pragma unroll
            for (int rp = 0; rp < 2; ++rp) {
                float2 c0 = unpack2(acc2[rp][0]);
                float2 c1 = unpack2(acc2[rp][1]);
                float2 c2 = unpack2(acc2[rp][2]);
                float2 c3 = unpack2(acc2[rp][3]);
                float4 vlo = make_float4(c0.x, c1.x, c2.x, c3.x);  // row 2rp
                float4 vhi = make_float4(c0.y, c1.y, c2.y, c3.y);  // row 2rp+1
                *(float4*)&red[s * 260 + (rg * 4 + 2 * rp + 0) * 16 + jq * 4] = vlo;
                *(float4*)&red[s * 260 + (rg * 4 + 2 * rp + 1) * 16 + jq * 4] = vhi;
            }
            __syncthreads();

            float sum = 0.0f;
            #pragma unroll
            for (int ss = 0; ss < 16; ++ss)
                sum += red[ss * 260 + out_lr * 16 + out_lj];

            float h = tanhf(sum + sZ[tt * 257 + tid]);
            g_abuf[t & 1][gr * 64 + gj] = h;    // compact state (next step's input)
            sA[tt * 257 + tid] = h;             // staged final-layout output

            if (t != T_X - 1) grid_barrier();   // includes leading __syncthreads
        }

        if (c == T_X / CH - 1) __syncthreads(); // last chunk lacks trailing barrier

        // Flush a chunk (coalesced float4 over t)
        #pragma unroll
        for (int i = 0; i < 2; ++i) {
            int e = tid + i * 256;
            int p = e >> 1;
            int q = e & 1;
            int lr2 = p >> 4, lj2 = p & 15;
            float4 v;
            v.x = sA[(q * 4 + 0) * 257 + p];
            v.y = sA[(q * 4 + 1) * 257 + p];
            v.z = sA[(q * 4 + 2) * 257 + p];
            v.w = sA[(q * 4 + 3) * 257 + p];
            *(float4*)(out_a + (size_t)(r0 + lr2) * NCOLS
                             + (j0 + lj2) * T_X + t0 + q * 4) = v;
        }
        // sA/sZ reuse next chunk ordered by next step's reduction __syncthreads
    }
}

// ---------------------------------------------------------------------------
// Softmax over the batch axis m (stride 1024 in memory), 64 elements/group.
// ---------------------------------------------------------------------------
__global__ void __launch_bounds__(256) softmax_batch(float* __restrict__ Y)
{
    int g = blockIdx.x * blockDim.x + threadIdx.x;   // 0 .. 512*1024-1
    int i = g >> 10, t = g & 1023;
    float* base = Y + (size_t)i * NCOLS + t;

    float v[64];
    float mx = -INFINITY;
    #pragma unroll
    for (int j = 0; j < 64; ++j) {
        v[j] = base[j * T_X];
        mx = fmaxf(mx, v[j]);
    }
    float sum = 0.0f;
    #pragma unroll
    for (int j = 0; j < 64; ++j) {
        v[j] = __expf(v[j] - mx);
        sum += v[j];
    }
    float inv = 1.0f / sum;
    #pragma unroll
    for (int j = 0; j < 64; ++j)
        base[j * T_X] = v[j] * inv;
}

// ---------------------------------------------------------------------------
// Launch: GEMM1 (Z into y-half of d_out) -> recurrence -> GEMM2 -> softmax
// ---------------------------------------------------------------------------
extern "C" void kernel_launch(void* const* d_in, const int* in_sizes, int n_in,
                              void* d_out, int out_size)
{
    const float* x   = (const float*)d_in[0];   // (512, 64, 1024) = 512 x 65536
    const float* a0  = (const float*)d_in[1];   // (512, 64)
    const float* Waa = (const float*)d_in[2];   // (512, 512)
    const float* Wax = (const float*)d_in[3];   // (512, 512)
    const float* Wya = (const float*)d_in[4];   // (512, 512)
    const float* ba  = (const float*)d_in[5];   // (512,)
    const float* by  = (const float*)d_in[6];   // (512,)

    float* out_a = (float*)d_out;               // first 512*64*1024 floats
    float* out_y = out_a + A_ELEMS;             // second half; also Z scratch

    dim3 gemm_grid(NCOLS / 128, N_A / 128);     // (512, 4)

    // 1) Z = Wax @ X + ba  (written into y-half, same [i, j*1024+t] layout)
    sgemm512_bias<<<gemm_grid, 256>>>(Wax, x, out_y, ba, NCOLS);

    // 2) sequential recurrence -> out_a
    rnn_recurrence<<<REC_BLOCKS, 256>>>(Waa, a0, out_y, out_a);

    // 3) logits = Wya @ A + by  (overwrites Z in y-half)
    sgemm512_bias<<<gemm_grid, 256>>>(Wya, out_a, out_y, by, NCOLS);

    // 4) softmax over batch axis
    softmax_batch<<<(N_X * T_X) / 256, 256>>>(out_y);
}

// round 16
// speedup vs baseline: 1.0116x; 1.0082x over previous
#include <cuda_runtime.h>
#include <math.h>

// Problem constants
#define N_A   512
#define N_X   512
#define T_X   1024
#define M_B   64
#define NCOLS 65536          // M_B * T_X
#define A_ELEMS 33554432     // 512*64*1024
#define CH    8              // timestep chunk staged in SMEM

// ---------------------------------------------------------------------------
// Packed f32x2 helpers (sm_103a FFMA2 — ptxas never auto-generates these)
// ---------------------------------------------------------------------------
__device__ __forceinline__ unsigned long long pack2(float lo, float hi) {
    unsigned long long r;
    asm("mov.b64 %0, {%1, %2};" : "=l"(r) : "f"(lo), "f"(hi));
    return r;
}
__device__ __forceinline__ float2 unpack2(unsigned long long v) {
    float2 r;
    asm("mov.b64 {%0, %1}, %2;" : "=f"(r.x), "=f"(r.y) : "l"(v));
    return r;
}
// d = a * b + d   (two independent fp32 FMAs per instruction)
__device__ __forceinline__ void fma2(unsigned long long& d,
                                     unsigned long long a,
                                     unsigned long long b) {
    asm("fma.rn.f32x2 %0, %1, %2, %3;" : "=l"(d) : "l"(a), "l"(b), "l"(d));
}

// ---------------------------------------------------------------------------
// Persistent-kernel state (small; endorsed scratch mechanism)
// ---------------------------------------------------------------------------
__device__ __align__(16) float g_abuf[2][N_A * M_B];  // ping-pong a_t (compact 512x64)
__device__ unsigned g_bar_cnt = 0;
__device__ unsigned g_bar_gen = 0;

#define REC_BLOCKS 128

// Light grid barrier: acquire/release atomics, no membar.gpu, no nanosleep.
__device__ __forceinline__ void grid_barrier() {
    __syncthreads();
    if (threadIdx.x == 0) {
        unsigned my;
        asm volatile("ld.acquire.gpu.u32 %0, [%1];"
                     : "=r"(my) : "l"(&g_bar_gen) : "memory");
        unsigned prev;
        asm volatile("atom.acq_rel.gpu.add.u32 %0, [%1], %2;"
                     : "=r"(prev) : "l"(&g_bar_cnt), "r"(1u) : "memory");
        if (prev == REC_BLOCKS - 1) {
            asm volatile("st.relaxed.gpu.u32 [%0], %1;"
                         :: "l"(&g_bar_cnt), "r"(0u) : "memory");
            asm volatile("red.release.gpu.add.u32 [%0], %1;"
                         :: "l"(&g_bar_gen), "r"(1u) : "memory");
        } else {
            unsigned g;
            do {
                asm volatile("ld.acquire.gpu.u32 %0, [%1];"
                             : "=r"(g) : "l"(&g_bar_gen) : "memory");
            } while (g == my);
        }
    }
    __syncthreads();
}

// ---------------------------------------------------------------------------
// SGEMM: C[512, N] = A[512,512] @ B[512, N] + bias[512]
// 128x128 CTA tile, BK=8, 256 threads, 8x8 per thread, double-buffered SMEM.
// Inner product uses FFMA2: accumulators paired across adjacent n-columns.
// FMA sequence per output element is identical to the scalar version
// (bitwise-identical results).
// ---------------------------------------------------------------------------
__global__ void __launch_bounds__(256) sgemm512_bias(
    const float* __restrict__ A, const float* __restrict__ B,
    float* __restrict__ C, const float* __restrict__ bias, int N)
{
    const int K = 512;
    __shared__ __align__(16) float As[2][8][128];
    __shared__ __align__(16) float Bs[2][8][128];

    int tid = threadIdx.x;
    int mBlock = blockIdx.y * 128;
    int nBlock = blockIdx.x * 128;

    int a_row = tid >> 1;
    int a_k4  = (tid & 1) << 2;
    int b_k   = tid >> 5;
    int b_col = (tid & 31) << 2;

    int tr = tid >> 4;            // 0..15
    int tc = tid & 15;            // 0..15
    int m0 = tr * 8, n0 = tc * 8;

    // acc2[r][p] = packed pair (C[r][2p], C[r][2p+1]); (0.0f,0.0f) == 0ull
    unsigned long long acc2[8][4];
    #pragma unroll
    for (int r = 0; r < 8; ++r)
        #pragma unroll
        for (int c = 0; c < 4; ++c) acc2[r][c] = 0ull;

    const float* Aptr = A + (size_t)(mBlock + a_row) * K + a_k4;
    const float* Bptr = B + (size_t)b_k * N + nBlock + b_col;

    // prologue: tile 0 -> buffer 0
    float4 av = *(const float4*)(Aptr);
    float4 bv = *(const float4*)(Bptr);
    As[0][a_k4 + 0][a_row] = av.x;
    As[0][a_k4 + 1][a_row] = av.y;
    As[0][a_k4 + 2][a_row] = av.z;
    As[0][a_k4 + 3][a_row] = av.w;
    *(float4*)&Bs[0][b_k][b_col] = bv;
    __syncthreads();

    for (int it = 0; it < K / 8; ++it) {
        int cur = it & 1;
        if (it < K / 8 - 1) {
            av = *(const float4*)(Aptr + (it + 1) * 8);
            bv = *(const float4*)(Bptr + (size_t)(it + 1) * 8 * N);
        }

        #pragma unroll
        for (int kk = 0; kk < 8; ++kk) {
            float4 a0v = *(const float4*)&As[cur][kk][m0];
            float4 a1v = *(const float4*)&As[cur][kk][m0 + 4];
            // B pairs read directly as b64 lanes (same LDS.128s as before)
            ulonglong2 b01 = *(const ulonglong2*)&Bs[cur][kk][n0];
            ulonglong2 b45 = *(const ulonglong2*)&Bs[cur][kk][n0 + 4];
            float am[8] = {a0v.x, a0v.y, a0v.z, a0v.w, a1v.x, a1v.y, a1v.z, a1v.w};
            #pragma unroll
            for (int r = 0; r < 8; ++r) {
                unsigned long long ar = pack2(am[r], am[r]);
                fma2(acc2[r][0], ar, b01.x);
                fma2(acc2[r][1], ar, b01.y);
                fma2(acc2[r][2], ar, b45.x);
                fma2(acc2[r][3], ar, b45.y);
            }
        }

        if (it < K / 8 - 1) {
            int nxt = cur ^ 1;
            As[nxt][a_k4 + 0][a_row] = av.x;
            As[nxt][a_k4 + 1][a_row] = av.y;
            As[nxt][a_k4 + 2][a_row] = av.z;
            As[nxt][a_k4 + 3][a_row] = av.w;
            *(float4*)&Bs[nxt][b_k][b_col] = bv;
            __syncthreads();
        }
    }

    #pragma unroll
    for (int r = 0; r < 8; ++r) {
        int row = mBlock + m0 + r;
        float bvl = bias[row];
        float* cp = C + (size_t)row * N + nBlock + n0;
        float2 p0 = unpack2(acc2[r][0]);
        float2 p1 = unpack2(acc2[r][1]);
        float2 p2 = unpack2(acc2[r][2]);
        float2 p3 = unpack2(acc2[r][3]);
        float4 o0 = make_float4(p0.x + bvl, p0.y + bvl, p1.x + bvl, p1.y + bvl);
        float4 o1 = make_float4(p2.x + bvl, p2.y + bvl, p3.x + bvl, p3.y + bvl);
        *(float4*)cp = o0;
        *(float4*)(cp + 4) = o1;
    }
}

// ---------------------------------------------------------------------------
// Recurrence: persistent kernel. 128 CTAs x 256 threads, 2D tiled.
// Grid = 32 row-groups x 4 col-groups; CTA tile = 16 rows x 16 cols.
// Waa block lives in REGISTERS as pre-packed f32x2 row pairs:
//   wlo[kk] = (Waa[r0+rg*4+0][k], Waa[r0+rg*4+1][k])
//   whi[kk] = (Waa[r0+rg*4+2][k], Waa[r0+rg*4+3][k])
// Per step per thread: 32 x LDG.128 of a_prev + 4 dup-packs + 8 FFMA2 per k
// (half the FMA-issue of the scalar version; identical FMA order per element).
// Z / a-output staged through SMEM in CH-step chunks.
// ---------------------------------------------------------------------------
__global__ void __launch_bounds__(256, 1) rnn_recurrence(
    const float* __restrict__ Waa, const float* __restrict__ a0,
    const float* __restrict__ Z, float* __restrict__ out_a)
{
    __shared__ __align__(16) float red[16 * 260];   // [s][lr*16+lj], padded
    __shared__ float sZ[CH * 257];                  // [tt][pair], padded
    __shared__ float sA[CH * 257];

    int tid = threadIdx.x;
    int rb = blockIdx.x >> 2;
    int cb = blockIdx.x & 3;
    int r0 = rb * 16;
    int j0 = cb * 16;

    int jq = tid & 3;          // col quad: cols j0 + jq*4 .. +3
    int rg = (tid >> 2) & 3;   // row group: rows r0 + rg*4 .. +3
    int s  = tid >> 4;         // k-slice: k in [32s, 32s+32)

    // Waa block -> packed registers (one-time; L1-served)
    unsigned long long wlo[32], whi[32];
    {
        const float* w0 = Waa + (size_t)(r0 + rg * 4 + 0) * 512 + s * 32;
        const float* w1 = Waa + (size_t)(r0 + rg * 4 + 1) * 512 + s * 32;
        const float* w2 = Waa + (size_t)(r0 + rg * 4 + 2) * 512 + s * 32;
        const float* w3 = Waa + (size_t)(r0 + rg * 4 + 3) * 512 + s * 32;
        #pragma unroll
        for (int kk = 0; kk < 32; ++kk) {
            wlo[kk] = pack2(w0[kk], w1[kk]);
            whi[kk] = pack2(w2[kk], w3[kk]);
        }
    }

    int out_lr = tid >> 4;     // 0..15 local row
    int out_lj = tid & 15;     // 0..15 local col
    int gr = r0 + out_lr;
    int gj = j0 + out_lj;

    int aq = (j0 >> 2) + jq;   // float4 column index into a_prev (64 floats/row)

    for (int c = 0; c < T_X / CH; ++c) {
        int t0 = c * CH;

        // Stage Z chunk: 16 lr x 16 lj x CH t  (two float4 per thread)
        #pragma unroll
        for (int i = 0; i < 2; ++i) {
            int e = tid + i * 256;
            int p = e >> 1;                 // pair 0..255: lr = p>>4, lj = p&15
            int q = e & 1;                  // which half of the 8 timesteps
            int lr2 = p >> 4, lj2 = p & 15;
            float4 v = *(const float4*)(Z + (size_t)(r0 + lr2) * NCOLS
                                          + (j0 + lj2) * T_X + t0 + q * 4);
            sZ[(q * 4 + 0) * 257 + p] = v.x;
            sZ[(q * 4 + 1) * 257 + p] = v.y;
            sZ[(q * 4 + 2) * 257 + p] = v.z;
            sZ[(q * 4 + 3) * 257 + p] = v.w;
        }
        // ordered before first use by step-0's reduction __syncthreads

        for (int tt = 0; tt < CH; ++tt) {
            int t = t0 + tt;
            const float4* ap4 = (const float4*)((t == 0) ? a0 : g_abuf[(t - 1) & 1]);

            // acc2[rp][cc] = packed rows (2rp, 2rp+1) for local column cc
            unsigned long long acc2[2][4];
            #pragma unroll
            for (int rp = 0; rp < 2; ++rp)
                #pragma unroll
                for (int cc = 0; cc < 4; ++cc) acc2[rp][cc] = 0ull;

            #pragma unroll
            for (int kk = 0; kk < 32; ++kk) {
                float4 avv = ap4[(s * 32 + kk) * 16 + aq];  // a_prev[k, 4 cols]
                unsigned long long ax = pack2(avv.x, avv.x);
                unsigned long long ay = pack2(avv.y, avv.y);
                unsigned long long az = pack2(avv.z, avv.z);
                unsigned long long aw = pack2(avv.w, avv.w);
                fma2(acc2[0][0], wlo[kk], ax);
                fma2(acc2[0][1], wlo[kk], ay);
                fma2(acc2[0][2], wlo[kk], az);
                fma2(acc2[0][3], wlo[kk], aw);
                fma2(acc2[1][0], whi[kk], ax);
                fma2(acc2[1][1], whi[kk], ay);
                fma2(acc2[1][2], whi[kk], az);
                fma2(acc2[1][3], whi[kk], aw);
            }

            // unpack + store partials: red[s][(rg*4+r)*16 + jq*4 .. +3]
            #pragma unroll
            for (int rp = 0; rp < 2; ++rp) {
                float2 c0 = unpack2(acc2[rp][0]);
                float2 c1 = unpack2(acc2[rp][1]);
                float2 c2 = unpack2(acc2[rp][2]);
                float2 c3 = unpack2(acc2[rp][3]);
                float4 vlo = make_float4(c0.x, c1.x, c2.x, c3.x);  // row 2rp
                float4 vhi = make_float4(c0.y, c1.y, c2.y, c3.y);  // row 2rp+1
                *(float4*)&red[s * 260 + (rg * 4 + 2 * rp + 0) * 16 + jq * 4] = vlo;
                *(float4*)&red[s * 260 + (rg * 4 + 2 * rp + 1) * 16 + jq * 4] = vhi;
            }
            __syncthreads();

            float sum = 0.0f;
            #pragma unroll
            for (int ss = 0; ss < 16; ++ss)
                sum += red[ss * 260 + out_lr * 16 + out_lj];

            float h = tanhf(sum + sZ[tt * 257 + tid]);
            g_abuf[t & 1][gr * 64 + gj] = h;    // compact state (next step's input)
            sA[tt * 257 + tid] = h;             // staged final-layout output

            if (t != T_X - 1) grid_barrier();   // includes leading __syncthreads
        }

        if (c == T_X / CH - 1) __syncthreads(); // last chunk lacks trailing barrier

        // Flush a chunk (coalesced float4 over t)
        #pragma unroll
        for (int i = 0; i < 2; ++i) {
            int e = tid + i * 256;
            int p = e >> 1;
            int q = e & 1;
            int lr2 = p >> 4, lj2 = p & 15;
            float4 v;
            v.x = sA[(q * 4 + 0) * 257 + p];
            v.y = sA[(q * 4 + 1) * 257 + p];
            v.z = sA[(q * 4 + 2) * 257 + p];
            v.w = sA[(q * 4 + 3) * 257 + p];
            *(float4*)(out_a + (size_t)(r0 + lr2) * NCOLS
                             + (j0 + lj2) * T_X + t0 + q * 4) = v;
        }
        // sA/sZ reuse next chunk ordered by next step's reduction __syncthreads
    }
}

// ---------------------------------------------------------------------------
// Softmax over the batch axis m (stride 1024 in memory), 64 elements/group.
// ---------------------------------------------------------------------------
__global__ void __launch_bounds__(256) softmax_batch(float* __restrict__ Y)
{
    int g = blockIdx.x * blockDim.x + threadIdx.x;   // 0 .. 512*1024-1
    int i = g >> 10, t = g & 1023;
    float* base = Y + (size_t)i * NCOLS + t;

    float v[64];
    float mx = -INFINITY;
    #pragma unroll
    for (int j = 0; j < 64; ++j) {
        v[j] = base[j * T_X];
        mx = fmaxf(mx, v[j]);
    }
    float sum = 0.0f;
    #pragma unroll
    for (int j = 0; j < 64; ++j) {
        v[j] = __expf(v[j] - mx);
        sum += v[j];
    }
    float inv = 1.0f / sum;
    #pragma unroll
    for (int j = 0; j < 64; ++j)
        base[j * T_X] = v[j] * inv;
}

// ---------------------------------------------------------------------------
// Launch: GEMM1 (Z into y-half of d_out) -> recurrence -> GEMM2 -> softmax
// ---------------------------------------------------------------------------
extern "C" void kernel_launch(void* const* d_in, const int* in_sizes, int n_in,
                              void* d_out, int out_size)
{
    const float* x   = (const float*)d_in[0];   // (512, 64, 1024) = 512 x 65536
    const float* a0  = (const float*)d_in[1];   // (512, 64)
    const float* Waa = (const float*)d_in[2];   // (512, 512)
    const float* Wax = (const float*)d_in[3];   // (512, 512)
    const float* Wya = (const float*)d_in[4];   // (512, 512)
    const float* ba  = (const float*)d_in[5];   // (512,)
    const float* by  = (const float*)d_in[6];   // (512,)

    float* out_a = (float*)d_out;               // first 512*64*1024 floats
    float* out_y = out_a + A_ELEMS;             // second half; also Z scratch

    dim3 gemm_grid(NCOLS / 128, N_A / 128);     // (512, 4)

    // 1) Z = Wax @ X + ba  (written into y-half, same [i, j*1024+t] layout)
    sgemm512_bias<<<gemm_grid, 256>>>(Wax, x, out_y, ba, NCOLS);

    // 2) sequential recurrence -> out_a
    rnn_recurrence<<<REC_BLOCKS, 256>>>(Waa, a0, out_y, out_a);

    // 3) logits = Wya @ A + by  (overwrites Z in y-half)
    sgemm512_bias<<<gemm_grid, 256>>>(Wya, out_a, out_y, by, NCOLS);

    // 4) softmax over batch axis
    softmax_batch<<<(N_X * T_X) / 256, 256>>>(out_y);
}